// round 5
// baseline (speedup 1.0000x reference)
#include <cuda_runtime.h>
#include <cuda_bf16.h>
#include <math.h>

// Problem shape (fixed by dataset)
#define B_ 4096
#define N_ 64
#define L_ 256
#define E_ 256

// ---------------------------------------------------------------------------
// Scratch (device globals; no allocation allowed)
// ---------------------------------------------------------------------------
__device__ float g_M[L_ * L_];       //  M = Wt^T @ Ws   [L,L]
__device__ float g_v[B_ * L_];       //  v = agent @ M^T [B,L]
__device__ float g_u[B_ * L_];       //  u = sum_n s_n * o[b,n,:]  [B,L]

// ---------------------------------------------------------------------------
// Kernel 1: M[l][lp] = sum_e Wt[e][l] * Ws[e][lp]
// grid (16,16), block (16,16)
// ---------------------------------------------------------------------------
__global__ void k_compute_M(const float* __restrict__ Wt,
                            const float* __restrict__ Ws,
                            float* __restrict__ M) {
    __shared__ float sT[16][17];
    __shared__ float sS[16][17];
    const int tx = threadIdx.x, ty = threadIdx.y;
    const int l  = blockIdx.y * 16 + ty;   // row of M
    const int lp = blockIdx.x * 16 + tx;   // col of M
    float acc = 0.0f;
    for (int e0 = 0; e0 < E_; e0 += 16) {
        sT[ty][tx] = Wt[(e0 + ty) * L_ + blockIdx.y * 16 + tx];
        sS[ty][tx] = Ws[(e0 + ty) * L_ + blockIdx.x * 16 + tx];
        __syncthreads();
#pragma unroll
        for (int e = 0; e < 16; e++)
            acc += sT[e][ty] * sS[e][tx];
        __syncthreads();
    }
    M[l * L_ + lp] = acc;
}

// ---------------------------------------------------------------------------
// Kernel 2/4: C[r][c] = sum_k A[r][k] * W[c][k]    (A @ W^T)
//   A: [Rows, 256], W: [256, 256], C: [Rows, 256]
// Tiling: BM=64, BN=64, BK=32, 256 threads, 4x4 per thread.
// grid: (256/BN, Rows/BM)
// ---------------------------------------------------------------------------
#define BM 64
#define BN 64
#define BK 32
__global__ void __launch_bounds__(256)
k_gemm_awt(const float* __restrict__ A,
           const float* __restrict__ W,
           float* __restrict__ C) {
    __shared__ float As[BK][BM + 4];   // k-major, stride 68 (16B aligned rows)
    __shared__ float Bs[BK][BN + 4];

    const int tid  = threadIdx.x;
    const int row0 = blockIdx.y * BM;
    const int col0 = blockIdx.x * BN;
    const int trow = (tid >> 4) * 4;   // 0..60
    const int tcol = (tid & 15) * 4;   // 0..60

    float acc[4][4];
#pragma unroll
    for (int i = 0; i < 4; i++)
#pragma unroll
        for (int j = 0; j < 4; j++) acc[i][j] = 0.0f;

    for (int k0 = 0; k0 < 256; k0 += BK) {
        // Load tiles (2048 floats each = 512 float4; 2 float4 per thread each)
#pragma unroll
        for (int p = 0; p < 2; p++) {
            int idx = tid + p * 256;        // 0..511
            int r   = idx >> 3;             // 0..63
            int kv  = (idx & 7) * 4;        // 0..28
            float4 va = *(const float4*)(A + (size_t)(row0 + r) * 256 + k0 + kv);
            As[kv + 0][r] = va.x; As[kv + 1][r] = va.y;
            As[kv + 2][r] = va.z; As[kv + 3][r] = va.w;
            float4 vb = *(const float4*)(W + (size_t)(col0 + r) * 256 + k0 + kv);
            Bs[kv + 0][r] = vb.x; Bs[kv + 1][r] = vb.y;
            Bs[kv + 2][r] = vb.z; Bs[kv + 3][r] = vb.w;
        }
        __syncthreads();

#pragma unroll
        for (int k = 0; k < BK; k++) {
            float4 av = *(const float4*)&As[k][trow];
            float4 bv = *(const float4*)&Bs[k][tcol];
            float a[4] = {av.x, av.y, av.z, av.w};
            float b[4] = {bv.x, bv.y, bv.z, bv.w};
#pragma unroll
            for (int i = 0; i < 4; i++)
#pragma unroll
                for (int j = 0; j < 4; j++)
                    acc[i][j] += a[i] * b[j];
        }
        __syncthreads();
    }

#pragma unroll
    for (int i = 0; i < 4; i++) {
        float4 o4 = make_float4(acc[i][0], acc[i][1], acc[i][2], acc[i][3]);
        *(float4*)(C + (size_t)(row0 + trow + i) * 256 + col0 + tcol) = o4;
    }
}

// ---------------------------------------------------------------------------
// Kernel 3: fused scores + softmax*hard + u
// One block per b (4096 blocks), 256 threads.
// Stages o[b] (64x256 f32 = 64KB) in smem once; used for both the score
// dot-products and the weighted sum u.
// ---------------------------------------------------------------------------
__global__ void __launch_bounds__(256)
k_attn(const float* __restrict__ opp,     // [B, N, L]
       const float* __restrict__ v,       // [B, L]
       const float* __restrict__ hard,    // [B, N]
       float* __restrict__ u,             // [B, L]
       float* __restrict__ scores_out) {  // [B, N]
    extern __shared__ float sm[];
    float* o_s = sm;                 // 64*256
    float* v_s = sm + N_ * L_;       // 256
    __shared__ float sc[N_];

    const int b    = blockIdx.x;
    const int tid  = threadIdx.x;
    const int warp = tid >> 5;
    const int lane = tid & 31;

    // load v[b]
    v_s[tid] = v[(size_t)b * L_ + tid];

    // load o[b]: 4096 float4, 16 per thread (coalesced)
    const float4* src = (const float4*)(opp + (size_t)b * N_ * L_);
    float4*       dst = (float4*)o_s;
#pragma unroll
    for (int i = 0; i < 16; i++)
        dst[tid + i * 256] = src[tid + i * 256];
    __syncthreads();

    // --- raw logits: 64 dots of length 256; warp w handles n = w*8+i ---
    float vr[8];
#pragma unroll
    for (int m = 0; m < 8; m++) vr[m] = v_s[lane + m * 32];

#pragma unroll
    for (int i = 0; i < 8; i++) {
        int n = warp * 8 + i;
        float s = 0.0f;
#pragma unroll
        for (int m = 0; m < 8; m++)
            s += o_s[n * L_ + lane + m * 32] * vr[m];
#pragma unroll
        for (int off = 16; off; off >>= 1)
            s += __shfl_xor_sync(0xffffffffu, s, off);
        if (lane == 0) sc[n] = s;
    }
    __syncthreads();

    // --- softmax over 64 + hard_attention multiply (warp 0) ---
    if (warp == 0) {
        float x0 = sc[lane];
        float x1 = sc[lane + 32];
        float mx = fmaxf(x0, x1);
#pragma unroll
        for (int off = 16; off; off >>= 1)
            mx = fmaxf(mx, __shfl_xor_sync(0xffffffffu, mx, off));
        float e0 = expf(x0 - mx);
        float e1 = expf(x1 - mx);
        float ssum = e0 + e1;
#pragma unroll
        for (int off = 16; off; off >>= 1)
            ssum += __shfl_xor_sync(0xffffffffu, ssum, off);
        float inv = 1.0f / ssum;
        float s0 = e0 * inv * hard[(size_t)b * N_ + lane];
        float s1 = e1 * inv * hard[(size_t)b * N_ + lane + 32];
        sc[lane]      = s0;
        sc[lane + 32] = s1;
        scores_out[(size_t)b * N_ + lane]      = s0;
        scores_out[(size_t)b * N_ + lane + 32] = s1;
    }
    __syncthreads();

    // --- u[b,l] = sum_n sc[n] * o[b,n,l] ---
    float acc = 0.0f;
#pragma unroll
    for (int n = 0; n < N_; n++)
        acc += sc[n] * o_s[n * L_ + tid];
    u[(size_t)b * L_ + tid] = acc;
}

// ---------------------------------------------------------------------------
// Launch
// ---------------------------------------------------------------------------
extern "C" void kernel_launch(void* const* d_in, const int* in_sizes, int n_in,
                              void* d_out, int out_size) {
    const float* agent = (const float*)d_in[0];   // [B, L]
    const float* opp   = (const float*)d_in[1];   // [B, N, L]
    const float* hard  = (const float*)d_in[2];   // [B, N]
    const float* Ws    = (const float*)d_in[3];   // [E, L]
    const float* Wt    = (const float*)d_in[4];   // [E, L]
    const float* Wc    = (const float*)d_in[5];   // [E, L]

    float* out        = (float*)d_out;
    float* result_out = out;                      // [B, E]
    float* scores_out = out + (size_t)B_ * E_;    // [B, N]

    float *dM, *dv, *du;
    cudaGetSymbolAddress((void**)&dM, g_M);
    cudaGetSymbolAddress((void**)&dv, g_v);
    cudaGetSymbolAddress((void**)&du, g_u);

    const int attn_smem = (N_ * L_ + L_) * (int)sizeof(float);  // 66,560 B
    cudaFuncSetAttribute(k_attn, cudaFuncAttributeMaxDynamicSharedMemorySize,
                         attn_smem);

    // 1. M = Wt^T @ Ws
    k_compute_M<<<dim3(L_ / 16, L_ / 16), dim3(16, 16)>>>(Wt, Ws, dM);

    // 2. v = agent @ M^T
    k_gemm_awt<<<dim3(L_ / BN, B_ / BM), 256>>>(agent, dM, dv);

    // 3. fused attention: scores (+ output) and u, one HBM pass over opp
    k_attn<<<B_, 256, attn_smem>>>(opp, dv, hard, du, scores_out);

    // 4. result = u @ Wc^T
    k_gemm_awt<<<dim3(E_ / BN, B_ / BM), 256>>>(du, Wc, result_out);
}

// round 6
// speedup vs baseline: 1.0072x; 1.0072x over previous
#include <cuda_runtime.h>
#include <cuda_bf16.h>
#include <math.h>

// Problem shape (fixed by dataset)
#define B_ 4096
#define N_ 64
#define L_ 256
#define E_ 256

// ---------------------------------------------------------------------------
// Scratch (device globals; no allocation allowed)
// ---------------------------------------------------------------------------
__device__ float g_M[L_ * L_];       //  M = Wt^T @ Ws   [L,L]
__device__ float g_v[B_ * L_];       //  v = agent @ M^T [B,L]
__device__ float g_u[B_ * L_];       //  u = sum_n s_n * o[b,n,:]  [B,L]

// ---------------------------------------------------------------------------
// Kernel 1: M[l][lp] = sum_e Wt[e][l] * Ws[e][lp]
// grid (16,16), block (16,16)
// ---------------------------------------------------------------------------
__global__ void k_compute_M(const float* __restrict__ Wt,
                            const float* __restrict__ Ws,
                            float* __restrict__ M) {
    __shared__ float sT[16][17];
    __shared__ float sS[16][17];
    const int tx = threadIdx.x, ty = threadIdx.y;
    const int l  = blockIdx.y * 16 + ty;   // row of M
    const int lp = blockIdx.x * 16 + tx;   // col of M
    float acc = 0.0f;
    for (int e0 = 0; e0 < E_; e0 += 16) {
        sT[ty][tx] = Wt[(e0 + ty) * L_ + blockIdx.y * 16 + tx];
        sS[ty][tx] = Ws[(e0 + ty) * L_ + blockIdx.x * 16 + tx];
        __syncthreads();
#pragma unroll
        for (int e = 0; e < 16; e++)
            acc += sT[e][ty] * sS[e][tx];
        __syncthreads();
    }
    M[l * L_ + lp] = acc;
}

// ---------------------------------------------------------------------------
// Kernel 2/4: C[r][c] = sum_k A[r][k] * W[c][k]    (A @ W^T)
//   A: [Rows, 256], W: [256, 256], C: [Rows, 256]
// Tiling: BM=64, BN=64, BK=32, 256 threads, 4x4 per thread.
// grid: (256/BN, Rows/BM)
// ---------------------------------------------------------------------------
#define BM 64
#define BN 64
#define BK 32
__global__ void __launch_bounds__(256)
k_gemm_awt(const float* __restrict__ A,
           const float* __restrict__ W,
           float* __restrict__ C) {
    __shared__ float As[BK][BM + 4];   // k-major, stride 68 (16B aligned rows)
    __shared__ float Bs[BK][BN + 4];

    const int tid  = threadIdx.x;
    const int row0 = blockIdx.y * BM;
    const int col0 = blockIdx.x * BN;
    const int trow = (tid >> 4) * 4;   // 0..60
    const int tcol = (tid & 15) * 4;   // 0..60

    float acc[4][4];
#pragma unroll
    for (int i = 0; i < 4; i++)
#pragma unroll
        for (int j = 0; j < 4; j++) acc[i][j] = 0.0f;

    for (int k0 = 0; k0 < 256; k0 += BK) {
        // Load tiles (2048 floats each = 512 float4; 2 float4 per thread each)
#pragma unroll
        for (int p = 0; p < 2; p++) {
            int idx = tid + p * 256;        // 0..511
            int r   = idx >> 3;             // 0..63
            int kv  = (idx & 7) * 4;        // 0..28
            float4 va = *(const float4*)(A + (size_t)(row0 + r) * 256 + k0 + kv);
            As[kv + 0][r] = va.x; As[kv + 1][r] = va.y;
            As[kv + 2][r] = va.z; As[kv + 3][r] = va.w;
            float4 vb = *(const float4*)(W + (size_t)(col0 + r) * 256 + k0 + kv);
            Bs[kv + 0][r] = vb.x; Bs[kv + 1][r] = vb.y;
            Bs[kv + 2][r] = vb.z; Bs[kv + 3][r] = vb.w;
        }
        __syncthreads();

#pragma unroll
        for (int k = 0; k < BK; k++) {
            float4 av = *(const float4*)&As[k][trow];
            float4 bv = *(const float4*)&Bs[k][tcol];
            float a[4] = {av.x, av.y, av.z, av.w};
            float b[4] = {bv.x, bv.y, bv.z, bv.w};
#pragma unroll
            for (int i = 0; i < 4; i++)
#pragma unroll
                for (int j = 0; j < 4; j++)
                    acc[i][j] += a[i] * b[j];
        }
        __syncthreads();
    }

#pragma unroll
    for (int i = 0; i < 4; i++) {
        float4 o4 = make_float4(acc[i][0], acc[i][1], acc[i][2], acc[i][3]);
        *(float4*)(C + (size_t)(row0 + trow + i) * 256 + col0 + tcol) = o4;
    }
}

// ---------------------------------------------------------------------------
// Kernel 3: fused scores + softmax*hard + u
// One block per b (4096 blocks), 256 threads.
// Stages o[b] (64x256 f32 = 64KB) in smem once; used for both the score
// dot-products and the weighted sum u.
// ---------------------------------------------------------------------------
__global__ void __launch_bounds__(256)
k_attn(const float* __restrict__ opp,     // [B, N, L]
       const float* __restrict__ v,       // [B, L]
       const float* __restrict__ hard,    // [B, N]
       float* __restrict__ u,             // [B, L]
       float* __restrict__ scores_out) {  // [B, N]
    extern __shared__ float sm[];
    float* o_s = sm;                 // 64*256
    float* v_s = sm + N_ * L_;       // 256
    __shared__ float sc[N_];

    const int b    = blockIdx.x;
    const int tid  = threadIdx.x;
    const int warp = tid >> 5;
    const int lane = tid & 31;

    // load v[b]
    v_s[tid] = v[(size_t)b * L_ + tid];

    // load o[b]: 4096 float4, 16 per thread (coalesced)
    const float4* src = (const float4*)(opp + (size_t)b * N_ * L_);
    float4*       dst = (float4*)o_s;
#pragma unroll
    for (int i = 0; i < 16; i++)
        dst[tid + i * 256] = src[tid + i * 256];
    __syncthreads();

    // --- raw logits: 64 dots of length 256; warp w handles n = w*8+i ---
    float vr[8];
#pragma unroll
    for (int m = 0; m < 8; m++) vr[m] = v_s[lane + m * 32];

#pragma unroll
    for (int i = 0; i < 8; i++) {
        int n = warp * 8 + i;
        float s = 0.0f;
#pragma unroll
        for (int m = 0; m < 8; m++)
            s += o_s[n * L_ + lane + m * 32] * vr[m];
#pragma unroll
        for (int off = 16; off; off >>= 1)
            s += __shfl_xor_sync(0xffffffffu, s, off);
        if (lane == 0) sc[n] = s;
    }
    __syncthreads();

    // --- softmax over 64 + hard_attention multiply (warp 0) ---
    if (warp == 0) {
        float x0 = sc[lane];
        float x1 = sc[lane + 32];
        float mx = fmaxf(x0, x1);
#pragma unroll
        for (int off = 16; off; off >>= 1)
            mx = fmaxf(mx, __shfl_xor_sync(0xffffffffu, mx, off));
        float e0 = expf(x0 - mx);
        float e1 = expf(x1 - mx);
        float ssum = e0 + e1;
#pragma unroll
        for (int off = 16; off; off >>= 1)
            ssum += __shfl_xor_sync(0xffffffffu, ssum, off);
        float inv = 1.0f / ssum;
        float s0 = e0 * inv * hard[(size_t)b * N_ + lane];
        float s1 = e1 * inv * hard[(size_t)b * N_ + lane + 32];
        sc[lane]      = s0;
        sc[lane + 32] = s1;
        scores_out[(size_t)b * N_ + lane]      = s0;
        scores_out[(size_t)b * N_ + lane + 32] = s1;
    }
    __syncthreads();

    // --- u[b,l] = sum_n sc[n] * o[b,n,l] ---
    float acc = 0.0f;
#pragma unroll
    for (int n = 0; n < N_; n++)
        acc += sc[n] * o_s[n * L_ + tid];
    u[(size_t)b * L_ + tid] = acc;
}

// ---------------------------------------------------------------------------
// Launch
// ---------------------------------------------------------------------------
extern "C" void kernel_launch(void* const* d_in, const int* in_sizes, int n_in,
                              void* d_out, int out_size) {
    const float* agent = (const float*)d_in[0];   // [B, L]
    const float* opp   = (const float*)d_in[1];   // [B, N, L]
    const float* hard  = (const float*)d_in[2];   // [B, N]
    const float* Ws    = (const float*)d_in[3];   // [E, L]
    const float* Wt    = (const float*)d_in[4];   // [E, L]
    const float* Wc    = (const float*)d_in[5];   // [E, L]

    float* out        = (float*)d_out;
    float* result_out = out;                      // [B, E]
    float* scores_out = out + (size_t)B_ * E_;    // [B, N]

    float *dM, *dv, *du;
    cudaGetSymbolAddress((void**)&dM, g_M);
    cudaGetSymbolAddress((void**)&dv, g_v);
    cudaGetSymbolAddress((void**)&du, g_u);

    const int attn_smem = (N_ * L_ + L_) * (int)sizeof(float);  // 66,560 B
    cudaFuncSetAttribute(k_attn, cudaFuncAttributeMaxDynamicSharedMemorySize,
                         attn_smem);

    // 1. M = Wt^T @ Ws
    k_compute_M<<<dim3(L_ / 16, L_ / 16), dim3(16, 16)>>>(Wt, Ws, dM);

    // 2. v = agent @ M^T
    k_gemm_awt<<<dim3(L_ / BN, B_ / BM), 256>>>(agent, dM, dv);

    // 3. fused attention: scores (+ output) and u, one HBM pass over opp
    k_attn<<<B_, 256, attn_smem>>>(opp, dv, hard, du, scores_out);

    // 4. result = u @ Wc^T
    k_gemm_awt<<<dim3(E_ / BN, B_ / BM), 256>>>(du, Wc, result_out);
}

// round 8
// speedup vs baseline: 1.2089x; 1.2003x over previous
#include <cuda_runtime.h>
#include <cuda_bf16.h>
#include <cstdint>
#include <math.h>

// Problem shape (fixed by dataset)
#define B_ 4096
#define N_ 64
#define L_ 256
#define E_ 256

// ---------------------------------------------------------------------------
// Scratch (device globals; no allocation allowed)
// ---------------------------------------------------------------------------
__device__ float g_M[L_ * L_];       //  M = Wt^T @ Ws   [L,L]
__device__ float g_v[B_ * L_];       //  v = agent @ M^T [B,L]
__device__ float g_u[B_ * L_];       //  u = sum_n s_n * o[b,n,:]  [B,L]

// ---------------------------------------------------------------------------
// cp.async helpers
// ---------------------------------------------------------------------------
__device__ __forceinline__ void cp16(unsigned int smem, const void* gmem) {
    asm volatile("cp.async.cg.shared.global [%0], [%1], 16;"
                 :: "r"(smem), "l"(__cvta_generic_to_global(gmem)));
}
__device__ __forceinline__ void cp4(unsigned int smem, const void* gmem) {
    asm volatile("cp.async.ca.shared.global [%0], [%1], 4;"
                 :: "r"(smem), "l"(__cvta_generic_to_global(gmem)));
}
#define CP_COMMIT() asm volatile("cp.async.commit_group;" ::: "memory")
#define CP_WAIT2()  asm volatile("cp.async.wait_group 2;" ::: "memory")

// ---------------------------------------------------------------------------
// Kernel 1: M[l][lp] = sum_e Wt[e][l] * Ws[e][lp]
// grid (16,16), block (16,16)
// ---------------------------------------------------------------------------
__global__ void k_compute_M(const float* __restrict__ Wt,
                            const float* __restrict__ Ws,
                            float* __restrict__ M) {
    __shared__ float sT[16][17];
    __shared__ float sS[16][17];
    const int tx = threadIdx.x, ty = threadIdx.y;
    const int l  = blockIdx.y * 16 + ty;
    const int lp = blockIdx.x * 16 + tx;
    float acc = 0.0f;
    for (int e0 = 0; e0 < E_; e0 += 16) {
        sT[ty][tx] = Wt[(e0 + ty) * L_ + blockIdx.y * 16 + tx];
        sS[ty][tx] = Ws[(e0 + ty) * L_ + blockIdx.x * 16 + tx];
        __syncthreads();
#pragma unroll
        for (int e = 0; e < 16; e++)
            acc += sT[e][ty] * sS[e][tx];
        __syncthreads();
    }
    M[l * L_ + lp] = acc;
}

// ---------------------------------------------------------------------------
// Kernel 2/4: C[r][c] = sum_k A[r][k] * W[c][k]    (A @ W^T)
// Double-buffered smem + register prefetch; ONE sync per K-tile.
// BM=64, BN=64, BK=32, 256 threads, 4x4 per thread.
// ---------------------------------------------------------------------------
#define BM 64
#define BN 64
#define BK 32
__global__ void __launch_bounds__(256)
k_gemm_awt(const float* __restrict__ A,
           const float* __restrict__ W,
           float* __restrict__ C) {
    __shared__ float As[2][BK][BM + 4];
    __shared__ float Bs[2][BK][BN + 4];

    const int tid  = threadIdx.x;
    const int row0 = blockIdx.y * BM;
    const int col0 = blockIdx.x * BN;
    const int trow = (tid >> 4) * 4;
    const int tcol = (tid & 15) * 4;

    // per-thread load coordinates (fixed across tiles)
    const int r0 = (tid)       >> 3;        // 0..31
    const int r1 = (tid + 256) >> 3;        // 32..63
    const int kv0 = (tid & 7) * 4;

    float acc[4][4];
#pragma unroll
    for (int i = 0; i < 4; i++)
#pragma unroll
        for (int j = 0; j < 4; j++) acc[i][j] = 0.0f;

    // prologue load of tile 0
    float4 va0 = *(const float4*)(A + (size_t)(row0 + r0) * 256 + 0 + kv0);
    float4 va1 = *(const float4*)(A + (size_t)(row0 + r1) * 256 + 0 + kv0);
    float4 vb0 = *(const float4*)(W + (size_t)(col0 + r0) * 256 + 0 + kv0);
    float4 vb1 = *(const float4*)(W + (size_t)(col0 + r1) * 256 + 0 + kv0);

#pragma unroll
    for (int t = 0; t < 8; t++) {
        const int buf = t & 1;
        // stage current tile
        As[buf][kv0 + 0][r0] = va0.x; As[buf][kv0 + 1][r0] = va0.y;
        As[buf][kv0 + 2][r0] = va0.z; As[buf][kv0 + 3][r0] = va0.w;
        As[buf][kv0 + 0][r1] = va1.x; As[buf][kv0 + 1][r1] = va1.y;
        As[buf][kv0 + 2][r1] = va1.z; As[buf][kv0 + 3][r1] = va1.w;
        Bs[buf][kv0 + 0][r0] = vb0.x; Bs[buf][kv0 + 1][r0] = vb0.y;
        Bs[buf][kv0 + 2][r0] = vb0.z; Bs[buf][kv0 + 3][r0] = vb0.w;
        Bs[buf][kv0 + 0][r1] = vb1.x; Bs[buf][kv0 + 1][r1] = vb1.y;
        Bs[buf][kv0 + 2][r1] = vb1.z; Bs[buf][kv0 + 3][r1] = vb1.w;
        __syncthreads();

        // prefetch next tile while computing this one
        if (t < 7) {
            const int k0 = (t + 1) * BK;
            va0 = *(const float4*)(A + (size_t)(row0 + r0) * 256 + k0 + kv0);
            va1 = *(const float4*)(A + (size_t)(row0 + r1) * 256 + k0 + kv0);
            vb0 = *(const float4*)(W + (size_t)(col0 + r0) * 256 + k0 + kv0);
            vb1 = *(const float4*)(W + (size_t)(col0 + r1) * 256 + k0 + kv0);
        }

#pragma unroll
        for (int k = 0; k < BK; k++) {
            float4 av = *(const float4*)&As[buf][k][trow];
            float4 bv = *(const float4*)&Bs[buf][k][tcol];
            float a[4] = {av.x, av.y, av.z, av.w};
            float b[4] = {bv.x, bv.y, bv.z, bv.w};
#pragma unroll
            for (int i = 0; i < 4; i++)
#pragma unroll
                for (int j = 0; j < 4; j++)
                    acc[i][j] += a[i] * b[j];
        }
        // no second sync: double buffer + the top-of-loop sync bounds skew < 1 iter
    }

#pragma unroll
    for (int i = 0; i < 4; i++) {
        float4 o4 = make_float4(acc[i][0], acc[i][1], acc[i][2], acc[i][3]);
        *(float4*)(C + (size_t)(row0 + trow + i) * 256 + col0 + tcol) = o4;
    }
}

// ---------------------------------------------------------------------------
// Kernel 3: persistent fused attention with 3-stage cp.async pipeline.
// Grid = #SMs, 512 threads. Per stage: o tile (64x256 f32 = 64KB) + v (1KB)
// + hard (256B). Three stages resident -> DRAM never starves.
// ---------------------------------------------------------------------------
#define STAGE_F (16384 + 256 + 64)          // floats per stage (16704)
#define ATTN_SMEM_F (3 * STAGE_F + 512)     // + upart
#define ATTN_SMEM_B (ATTN_SMEM_F * 4)       // 202,496 bytes

__global__ void __launch_bounds__(512, 1)
k_attn2(const float* __restrict__ opp,     // [B, N, L]
        const float* __restrict__ v,       // [B, L]
        const float* __restrict__ hard,    // [B, N]
        float* __restrict__ u,             // [B, L]
        float* __restrict__ scores_out) {  // [B, N]
    extern __shared__ float sm[];
    float* upart = sm + 3 * STAGE_F;
    __shared__ float sc[N_];

    const int tid  = threadIdx.x;
    const int warp = tid >> 5;
    const int lane = tid & 31;
    const int gs   = gridDim.x;
    const unsigned int smem_base = (unsigned int)__cvta_generic_to_shared(sm);

    // issue one pipeline stage (always commits a group, possibly empty)
    auto issue = [&](int s, int bb) {
        if (bb < B_) {
            const float* ob = opp + (size_t)bb * (N_ * L_);
            const unsigned int so = smem_base + (unsigned int)(s * STAGE_F) * 4u;
#pragma unroll
            for (int j = 0; j < 8; j++) {
                int q = tid + j * 512;                 // float4 index
                cp16(so + (unsigned int)q * 16u, ob + q * 4);
            }
            if (tid < 256)
                cp4(so + (unsigned int)(16384 + tid) * 4u, v + (size_t)bb * L_ + tid);
            if (tid < 64)
                cp4(so + (unsigned int)(16384 + 256 + tid) * 4u, hard + (size_t)bb * N_ + tid);
        }
        CP_COMMIT();
    };

    // prologue: fill 3 stages
    issue(0, blockIdx.x);
    issue(1, blockIdx.x + gs);
    issue(2, blockIdx.x + 2 * gs);

    int s = 0;
    for (int b = blockIdx.x; b < B_; b += gs) {
        CP_WAIT2();            // oldest group (stage s) complete
        __syncthreads();       // make it visible to all threads

        const float* o_s = sm + s * STAGE_F;
        const float* v_s = o_s + 16384;
        const float* h_s = v_s + 256;

        // --- logits: warp w handles n = w*4 + i ---
        float vr[8];
#pragma unroll
        for (int m = 0; m < 8; m++) vr[m] = v_s[lane + m * 32];

#pragma unroll
        for (int i = 0; i < 4; i++) {
            const int n = (warp << 2) + i;
            float sd = 0.0f;
#pragma unroll
            for (int m = 0; m < 8; m++)
                sd = fmaf(o_s[n * L_ + lane + m * 32], vr[m], sd);
#pragma unroll
            for (int off = 16; off; off >>= 1)
                sd += __shfl_xor_sync(0xffffffffu, sd, off);
            if (lane == 0) sc[n] = sd;
        }
        __syncthreads();

        // --- softmax over 64 + hard multiply (warp 0) ---
        if (warp == 0) {
            float x0 = sc[lane];
            float x1 = sc[lane + 32];
            float mx = fmaxf(x0, x1);
#pragma unroll
            for (int off = 16; off; off >>= 1)
                mx = fmaxf(mx, __shfl_xor_sync(0xffffffffu, mx, off));
            float e0 = expf(x0 - mx);
            float e1 = expf(x1 - mx);
            float ssum = e0 + e1;
#pragma unroll
            for (int off = 16; off; off >>= 1)
                ssum += __shfl_xor_sync(0xffffffffu, ssum, off);
            float inv = 1.0f / ssum;
            float s0 = e0 * inv * h_s[lane];
            float s1 = e1 * inv * h_s[lane + 32];
            sc[lane]      = s0;
            sc[lane + 32] = s1;
            scores_out[(size_t)b * N_ + lane]      = s0;
            scores_out[(size_t)b * N_ + lane + 32] = s1;
        }
        __syncthreads();

        // --- u[b,l] = sum_n sc[n] * o[b,n,l] (split over 2 thread halves) ---
        {
            const int l    = tid & 255;
            const int half = tid >> 8;
            const float* op = o_s + half * 32 * L_ + l;
            float acc = 0.0f;
#pragma unroll
            for (int n = 0; n < 32; n++)
                acc = fmaf(sc[half * 32 + n], op[n * L_], acc);
            upart[tid] = acc;
        }
        __syncthreads();       // all reads of stage s are now complete
        if (tid < 256)
            u[(size_t)b * L_ + tid] = upart[tid] + upart[tid + 256];

        // reuse freed stage for tile b + 3*gs
        issue(s, b + 3 * gs);
        s = (s == 2) ? 0 : s + 1;
    }
}

// ---------------------------------------------------------------------------
// Launch
// ---------------------------------------------------------------------------
extern "C" void kernel_launch(void* const* d_in, const int* in_sizes, int n_in,
                              void* d_out, int out_size) {
    const float* agent = (const float*)d_in[0];   // [B, L]
    const float* opp   = (const float*)d_in[1];   // [B, N, L]
    const float* hard  = (const float*)d_in[2];   // [B, N]
    const float* Ws    = (const float*)d_in[3];   // [E, L]
    const float* Wt    = (const float*)d_in[4];   // [E, L]
    const float* Wc    = (const float*)d_in[5];   // [E, L]

    float* out        = (float*)d_out;
    float* result_out = out;                      // [B, E]
    float* scores_out = out + (size_t)B_ * E_;    // [B, N]

    float *dM, *dv, *du;
    cudaGetSymbolAddress((void**)&dM, g_M);
    cudaGetSymbolAddress((void**)&dv, g_v);
    cudaGetSymbolAddress((void**)&du, g_u);

    int dev = 0, nsm = 148;
    cudaGetDevice(&dev);
    cudaDeviceGetAttribute(&nsm, cudaDevAttrMultiProcessorCount, dev);

    cudaFuncSetAttribute(k_attn2, cudaFuncAttributeMaxDynamicSharedMemorySize,
                         ATTN_SMEM_B);

    // 1. M = Wt^T @ Ws
    k_compute_M<<<dim3(L_ / 16, L_ / 16), dim3(16, 16)>>>(Wt, Ws, dM);

    // 2. v = agent @ M^T
    k_gemm_awt<<<dim3(L_ / BN, B_ / BM), 256>>>(agent, dM, dv);

    // 3. persistent pipelined attention: one HBM pass over opp
    k_attn2<<<nsm, 512, ATTN_SMEM_B>>>(opp, dv, hard, du, scores_out);

    // 4. result = u @ Wc^T
    k_gemm_awt<<<dim3(E_ / BN, B_ / BM), 256>>>(du, Wc, result_out);
}